// round 3
// baseline (speedup 1.0000x reference)
#include <cuda_runtime.h>
#include <cuda_bf16.h>
#include <cstdint>

// Problem constants (from reference):
//   N_NODES = 50000, N_EDGES = 800000, D_FEAT = 64
//   m = x[src] * e          [E, 64]
//   out = segment_sum(m, dst, N_NODES)   [N, 64]

#define D_FEAT 64
#define F4_PER_ROW (D_FEAT / 4)   // 16 float4 per feature row

__global__ void scatter_sum_kernel(const float* __restrict__ x,
                                   const float* __restrict__ e,
                                   const int*   __restrict__ src,
                                   const int*   __restrict__ dst,
                                   float* __restrict__ out,
                                   int n_edges) {
    int tid  = blockIdx.x * blockDim.x + threadIdx.x;
    int edge = tid >> 4;          // 16 threads per edge
    int f4   = tid & 15;          // which float4 of the 64-float row
    if (edge >= n_edges) return;

    int   s = src[edge];
    int   d = dst[edge];
    float w = e[edge];

    // Coalesced-ish gather: the 16 threads of an edge read 16 consecutive
    // float4s of row x[s]; a warp covers 2 rows in 64B contiguous chunks.
    const float4* xrow = reinterpret_cast<const float4*>(x + (size_t)s * D_FEAT);
    float4 xv = __ldg(xrow + f4);

    float4 m;
    m.x = xv.x * w;
    m.y = xv.y * w;
    m.z = xv.z * w;
    m.w = xv.w * w;

    // Vectorized fp32 reduction (sm_90+): one 16B L2 atomic instead of four 4B.
    float* addr = out + (size_t)d * D_FEAT + f4 * 4;
    asm volatile("red.global.add.v4.f32 [%0], {%1, %2, %3, %4};"
                 :: "l"(addr), "f"(m.x), "f"(m.y), "f"(m.z), "f"(m.w)
                 : "memory");
}

extern "C" void kernel_launch(void* const* d_in, const int* in_sizes, int n_in,
                              void* d_out, int out_size) {
    // Identify inputs by element count (robust whether scalar `t` is
    // materialized as an input or not):
    //   x           : 50000*64 = 3,200,000 elems (float)
    //   e, src, dst : 800,000 elems each, in metadata order e -> src -> dst
    const float* x   = nullptr;
    const float* e   = nullptr;
    const int*   src = nullptr;
    const int*   dst = nullptr;
    int n_edges = 0;

    int big_seen = 0;
    for (int i = 0; i < n_in; i++) {
        int sz = in_sizes[i];
        if (sz >= 1000000) {                     // x
            x = (const float*)d_in[i];
        } else if (sz >= 100000) {               // e, src, dst (800000 each)
            n_edges = sz;
            if (big_seen == 0)      e   = (const float*)d_in[i];
            else if (big_seen == 1) src = (const int*)d_in[i];
            else                    dst = (const int*)d_in[i];
            big_seen++;
        }
        // sz == 1 (t) ignored
    }

    // Output is poisoned to 0xAA — zero it before accumulation.
    cudaMemsetAsync(d_out, 0, (size_t)out_size * sizeof(float));

    int total_threads = n_edges * F4_PER_ROW;   // 12.8M
    int block = 256;
    int grid  = (total_threads + block - 1) / block;
    scatter_sum_kernel<<<grid, block>>>(x, e, src, dst, (float*)d_out, n_edges);
}